// round 14
// baseline (speedup 1.0000x reference)
#include <cuda_runtime.h>

#define NB      2
#define RB      36          // NB * 18 rows per CTA
#define THREADS 128
#define TSTEPS  128
#define NNODE   18
#define DIMX    32
#define HIDN    64
#define STF     132         // feature-buffer row stride (floats), padded
#define STH     68          // hidden-state row stride
#define NBLK    256         // grid: 512 / NB
#define STS2    24          // St2 row stride in float2

typedef unsigned long long u64;

// ---------------- packed f32x2 helpers ----------------
__device__ __forceinline__ u64 pk2(float a, float b) {
    u64 r;
    asm("mov.b64 %0, {%1, %2};" : "=l"(r)
        : "r"(__float_as_uint(a)), "r"(__float_as_uint(b)));
    return r;
}
__device__ __forceinline__ float2 up2(u64 v) {
    unsigned lo, hi;
    asm("mov.b64 {%0, %1}, %2;" : "=r"(lo), "=r"(hi) : "l"(v));
    return make_float2(__uint_as_float(lo), __uint_as_float(hi));
}
__device__ __forceinline__ void fma2(u64 &d, u64 a, u64 b) {
    asm("fma.rn.f32x2 %0, %1, %2, %0;" : "+l"(d) : "l"(a), "l"(b));
}
__device__ __forceinline__ void add2(u64 &d, u64 a) {
    asm("add.rn.f32x2 %0, %0, %1;" : "+l"(d) : "l"(a));
}

// ---------------- approx transcendentals ----------------
__device__ __forceinline__ float ex2f(float x) {
    float r; asm("ex2.approx.ftz.f32 %0, %1;" : "=f"(r) : "f"(x)); return r;
}
__device__ __forceinline__ float rcpf(float x) {
    float r; asm("rcp.approx.ftz.f32 %0, %1;" : "=f"(r) : "f"(x)); return r;
}
__device__ __forceinline__ float sigm(float v) {
    return rcpf(1.f + ex2f(-1.4426950408889634f * v));
}
__device__ __forceinline__ float tanh_(float v) {
    return 1.f - 2.f * rcpf(1.f + ex2f(2.8853900817779268f * v));
}

// ---------------- shared memory layout ----------------
struct __align__(16) Smem {
    float2 St2[2][NNODE * STS2]; // transposed supports, duplicated pairs
    float hA[RB * STH];
    float hB[RB * STH];
    float Z[RB * STF];          // concat input (gate Z; becomes cand Z in-place)
    float Da[RB * STF];         // Chebyshev x1 (aliases reduce scratch when dead)
    float Db[RB * STF];         // Chebyshev x2
    float OUT[RB * STF];        // gate output; only u-half (cols 64..127) used
};
// sizeof = 102528 B  -> 2 CTAs/SM (205 KB <= 227 KB dyn-smem limit)

// ---------------- spmm (4 cols/thread): dst = S @ src  (or 2*S@src - Zsub) ----
__device__ __forceinline__ void spmm4(const float2* __restrict__ St,
                                      const float* __restrict__ src,
                                      float* __restrict__ dst,
                                      const float* __restrict__ zsub,
                                      int CC, int rbase, int bloc, int nlo,
                                      int c0)
{
    if (c0 >= CC) return;
    const float* srcb = src + bloc * NNODE * STF + c0;
    u64 a[18];
#pragma unroll
    for (int i = 0; i < 18; i++) a[i] = 0;
    ulonglong2 z = *(const ulonglong2*)(srcb);   // depth-1 prefetch
#pragma unroll 1
    for (int mm = 0; mm < NNODE; mm++) {
        ulonglong2 zc = z;
        if (mm + 1 < NNODE) z = *(const ulonglong2*)(srcb + (mm + 1) * STF);
        const float2* sp = St + mm * STS2 + nlo;
        ulonglong2 p01 = *(const ulonglong2*)(sp);
        ulonglong2 p23 = *(const ulonglong2*)(sp + 2);
        ulonglong2 p45 = *(const ulonglong2*)(sp + 4);
        ulonglong2 p67 = *(const ulonglong2*)(sp + 6);
        u64        p8  = *(const u64*)(sp + 8);
        fma2(a[0],  p01.x, zc.x); fma2(a[1],  p01.x, zc.y);
        fma2(a[2],  p01.y, zc.x); fma2(a[3],  p01.y, zc.y);
        fma2(a[4],  p23.x, zc.x); fma2(a[5],  p23.x, zc.y);
        fma2(a[6],  p23.y, zc.x); fma2(a[7],  p23.y, zc.y);
        fma2(a[8],  p45.x, zc.x); fma2(a[9],  p45.x, zc.y);
        fma2(a[10], p45.y, zc.x); fma2(a[11], p45.y, zc.y);
        fma2(a[12], p67.x, zc.x); fma2(a[13], p67.x, zc.y);
        fma2(a[14], p67.y, zc.x); fma2(a[15], p67.y, zc.y);
        fma2(a[16], p8,    zc.x); fma2(a[17], p8,    zc.y);
    }
#pragma unroll
    for (int i = 0; i < 9; i++) {
        float2 q0 = up2(a[2 * i]), q1 = up2(a[2 * i + 1]);
        float4 o;
        if (zsub) {
            float4 zz = *(const float4*)(zsub + (rbase + i) * STF + c0);
            o = make_float4(2.f * q0.x - zz.x, 2.f * q0.y - zz.y,
                            2.f * q1.x - zz.z, 2.f * q1.y - zz.w);
        } else {
            o = make_float4(q0.x, q0.y, q1.x, q1.y);
        }
        *(float4*)(dst + (rbase + i) * STF + c0) = o;
    }
}

// ---------------- W loaders ----------------
__device__ __forceinline__ void ldwg(const float* p, ulonglong2 w[8]) {
#pragma unroll
    for (int kk = 0; kk < 4; kk++) {
        w[2 * kk]     = __ldg((const ulonglong2*)(p + kk * 128));
        w[2 * kk + 1] = __ldg((const ulonglong2*)(p + kk * 128 + 4));
    }
}
__device__ __forceinline__ void ldwc(const float* p, ulonglong2 w[4]) {
#pragma unroll
    for (int kk = 0; kk < 4; kk++)
        w[kk] = __ldg((const ulonglong2*)(p + kk * 64));
}

// gate GEMM k-slice: 9 rows x 8 cols per thread (16 fma2 per feat LDS.128)
template<int CC>
__device__ __forceinline__ void gemm_gate(const float* __restrict__ feat,
                                          const float* __restrict__ W,
                                          int kbeg, int c8, int rbase,
                                          u64 acc[36])
{
    constexpr int G = CC / 8;   // 4-k groups in this k-half
    const float* wp = W + (size_t)kbeg * 128 + c8;
    ulonglong2 wc[8], wn[8];
    ldwg(wp, wc);
#pragma unroll 2
    for (int g = 0; g < G; g++) {
        if (g + 1 < G) ldwg(wp + (size_t)(g + 1) * 512, wn);
        const float* fp = feat + rbase * STF + kbeg + 4 * g;
#pragma unroll
        for (int i = 0; i < 9; i++) {
            float4 f = *(const float4*)(fp + i * STF);
            u64 f0 = pk2(f.x, f.x), f1 = pk2(f.y, f.y);
            u64 f2 = pk2(f.z, f.z), f3 = pk2(f.w, f.w);
            fma2(acc[4 * i + 0], f0, wc[0].x); fma2(acc[4 * i + 1], f0, wc[0].y);
            fma2(acc[4 * i + 2], f0, wc[1].x); fma2(acc[4 * i + 3], f0, wc[1].y);
            fma2(acc[4 * i + 0], f1, wc[2].x); fma2(acc[4 * i + 1], f1, wc[2].y);
            fma2(acc[4 * i + 2], f1, wc[3].x); fma2(acc[4 * i + 3], f1, wc[3].y);
            fma2(acc[4 * i + 0], f2, wc[4].x); fma2(acc[4 * i + 1], f2, wc[4].y);
            fma2(acc[4 * i + 2], f2, wc[5].x); fma2(acc[4 * i + 3], f2, wc[5].y);
            fma2(acc[4 * i + 0], f3, wc[6].x); fma2(acc[4 * i + 1], f3, wc[6].y);
            fma2(acc[4 * i + 2], f3, wc[7].x); fma2(acc[4 * i + 3], f3, wc[7].y);
        }
#pragma unroll
        for (int q = 0; q < 8; q++) wc[q] = wn[q];
    }
}

// cand GEMM k-slice: 9 rows x 4 cols per thread
template<int CC>
__device__ __forceinline__ void gemm_cand(const float* __restrict__ feat,
                                          const float* __restrict__ W,
                                          int kbeg, int c4, int rbase,
                                          u64 acc[18])
{
    constexpr int G = CC / 8;
    const float* wp = W + (size_t)kbeg * 64 + c4;
    ulonglong2 wc[4], wn[4];
    ldwc(wp, wc);
#pragma unroll 2
    for (int g = 0; g < G; g++) {
        if (g + 1 < G) ldwc(wp + (size_t)(g + 1) * 256, wn);
        const float* fp = feat + rbase * STF + kbeg + 4 * g;
#pragma unroll
        for (int i = 0; i < 9; i++) {
            float4 f = *(const float4*)(fp + i * STF);
            fma2(acc[2 * i],     pk2(f.x, f.x), wc[0].x);
            fma2(acc[2 * i + 1], pk2(f.x, f.x), wc[0].y);
            fma2(acc[2 * i],     pk2(f.y, f.y), wc[1].x);
            fma2(acc[2 * i + 1], pk2(f.y, f.y), wc[1].y);
            fma2(acc[2 * i],     pk2(f.z, f.z), wc[2].x);
            fma2(acc[2 * i + 1], pk2(f.z, f.z), wc[2].y);
            fma2(acc[2 * i],     pk2(f.w, f.w), wc[3].x);
            fma2(acc[2 * i + 1], pk2(f.w, f.w), wc[3].y);
        }
#pragma unroll
        for (int q = 0; q < 4; q++) wc[q] = wn[q];
    }
}

// ---------------- main persistent kernel ----------------
__global__ void __launch_bounds__(THREADS, 2)
dcrnn_kernel(const float* __restrict__ x,   const float* __restrict__ sup,
             const float* __restrict__ wg0, const float* __restrict__ bg0,
             const float* __restrict__ wc0, const float* __restrict__ bc0,
             const float* __restrict__ wg1, const float* __restrict__ bg1,
             const float* __restrict__ wc1, const float* __restrict__ bc1,
             const float* __restrict__ fcw, const float* __restrict__ fcb,
             float* __restrict__ out)
{
    extern __shared__ char smraw[];
    Smem& sm = *reinterpret_cast<Smem*>(smraw);

    const int tid   = threadIdx.x;
    const int bbase = blockIdx.x * NB;
    // gemm map: 4 rowg x 16 colg x 2 khalf = 128 threads
    const int rowg  = tid & 3;            // 4 row groups of 9 rows
    const int colg  = (tid >> 2) & 15;    // 16 col groups
    const int khalf = tid >> 6;           // k-slice half
    const int c8    = 8 * colg;           // gate col base
    const int c4    = 4 * colg;           // cand col base
    const int rbase = rowg * 9;
    const int bloc  = rowg >> 1;          // local batch of this thread's rows
    const int nlo   = (rowg & 1) ? 12 : 0; // St2 lane base
    // spmm map: 4 rowg x 32 col-quads
    const int rowg_s  = tid & 3;
    const int c0_s    = 4 * (tid >> 2);   // 0..124
    const int rbase_s = 9 * rowg_s;
    const int bloc_s  = rowg_s >> 1;
    const int nlo_s   = (rowg_s & 1) ? 12 : 0;

    u64* const scr = (u64*)sm.Da;         // reduce scratch aliases Da (dead then)

    // init: transpose + duplicate supports into St2
    for (int i = tid; i < 2 * NNODE * NNODE; i += THREADS) {
        int s = i / (NNODE * NNODE);
        int rem = i - s * NNODE * NNODE;
        int n = rem / NNODE;              // row of S
        int m = rem - n * NNODE;          // col of S
        float v = sup[i];
        int lane = (n < 9) ? n : (12 + n - 9);
        sm.St2[s][m * STS2 + lane] = make_float2(v, v);
    }
    for (int i = tid; i < RB * STH; i += THREADS) { sm.hA[i] = 0.f; sm.hB[i] = 0.f; }
    __syncthreads();

    for (int t = 0; t < TSTEPS; t++) {
        for (int cell = 0; cell < 2; cell++) {
            const int CC  = cell ? 128 : 96;
            const int CCH = CC >> 1;
            const int kbeg = khalf * CCH;
            const int hoff = cell ? HIDN : DIMX;   // offset of h-region in Z
            const float* WG = cell ? wg1 : wg0;
            const float* BG = cell ? bg1 : bg0;
            const float* WC = cell ? wc1 : wc0;
            const float* BC = cell ? bc1 : bc0;
            float* H = cell ? sm.hB : sm.hA;       // this cell's own state

            // ============ gate Z build: Z = [input | H] ============
            if (cell == 0) {
                // x loaded straight from gmem into Z
                for (int j = tid; j < RB * 24; j += THREADS) {
                    int r = j / 24, c = 4 * (j - 24 * r);
                    float4 v;
                    if (c < DIMX) {
                        int b = bbase + r / NNODE;
                        int n = r - NNODE * (r / NNODE);
                        v = *(const float4*)(x +
                            (((size_t)b * TSTEPS + t) * NNODE + n) * DIMX + c);
                    } else {
                        v = *(const float4*)(sm.hA + r * STH + (c - DIMX));
                    }
                    *(float4*)(sm.Z + r * STF + c) = v;
                }
            } else {
                for (int j = tid; j < RB * 32; j += THREADS) {
                    int r = j >> 5, c = 4 * (j & 31);
                    float4 v = (c < HIDN)
                        ? *(const float4*)(sm.hA + r * STH + c)
                        : *(const float4*)(sm.hB + r * STH + (c - HIDN));
                    *(float4*)(sm.Z + r * STF + c) = v;
                }
            }
            __syncthreads();

            // ============ GATE dconv + fused cand-Z build ============
            {
                u64 ga[36];
#pragma unroll
                for (int q = 0; q < 36; q++) ga[q] = 0;
#pragma unroll 1
                for (int m = 0; m < 5; m++) {
                    const float* feat;
                    if (m == 0) feat = sm.Z;
                    else {
                        int s = (m - 1) >> 1;
                        int second = (m - 1) & 1;
                        const float* src = second ? sm.Da : sm.Z;
                        float* dst = second ? sm.Db : sm.Da;
                        spmm4(sm.St2[s], src, dst,
                              second ? sm.Z : (const float*)0,
                              CC, rbase_s, bloc_s, nlo_s, c0_s);
                        __syncthreads();
                        feat = dst;
                    }
                    if (cell) gemm_gate<128>(feat, WG + (size_t)m * 128 * 128,
                                             kbeg, c8, rbase, ga);
                    else      gemm_gate<96> (feat, WG + (size_t)m * 96 * 128,
                                             kbeg, c8, rbase, ga);
                }
                __syncthreads();              // gemm done; Da/Db dead
                if (khalf) {
                    u64* s = scr + (size_t)(tid - 64) * 36;
#pragma unroll
                    for (int q = 0; q < 36; q++) s[q] = ga[q];
                }
                __syncthreads();
                if (!khalf) {
                    const u64* s = scr + (size_t)tid * 36;
#pragma unroll
                    for (int q = 0; q < 36; q++) add2(ga[q], s[q]);
                    float4 b0 = *(const float4*)(BG + c8);
                    float4 b1 = *(const float4*)(BG + c8 + 4);
                    if (c8 < HIDN) {
                        // r-part: write Z[r][hoff+c] = sigm(.)*H_prev[r][c]
#pragma unroll
                        for (int i = 0; i < 9; i++) {
                            int r = rbase + i;
                            float2 q0 = up2(ga[4 * i]),     q1 = up2(ga[4 * i + 1]);
                            float2 q2 = up2(ga[4 * i + 2]), q3 = up2(ga[4 * i + 3]);
                            float4 h0 = *(const float4*)(H + r * STH + c8);
                            float4 h1 = *(const float4*)(H + r * STH + c8 + 4);
                            float4 o0 = make_float4(sigm(q0.x + b0.x) * h0.x,
                                                    sigm(q0.y + b0.y) * h0.y,
                                                    sigm(q1.x + b0.z) * h0.z,
                                                    sigm(q1.y + b0.w) * h0.w);
                            float4 o1 = make_float4(sigm(q2.x + b1.x) * h1.x,
                                                    sigm(q2.y + b1.y) * h1.y,
                                                    sigm(q3.x + b1.z) * h1.z,
                                                    sigm(q3.y + b1.w) * h1.w);
                            *(float4*)(sm.Z + r * STF + hoff + c8)     = o0;
                            *(float4*)(sm.Z + r * STF + hoff + c8 + 4) = o1;
                        }
                    } else {
                        // u-part: store to OUT cols 64..127
#pragma unroll
                        for (int i = 0; i < 9; i++) {
                            int r = rbase + i;
                            float2 q0 = up2(ga[4 * i]),     q1 = up2(ga[4 * i + 1]);
                            float2 q2 = up2(ga[4 * i + 2]), q3 = up2(ga[4 * i + 3]);
                            float4 o0 = make_float4(sigm(q0.x + b0.x), sigm(q0.y + b0.y),
                                                    sigm(q1.x + b0.z), sigm(q1.y + b0.w));
                            float4 o1 = make_float4(sigm(q2.x + b1.x), sigm(q2.y + b1.y),
                                                    sigm(q3.x + b1.z), sigm(q3.y + b1.w));
                            *(float4*)(sm.OUT + r * STF + c8)     = o0;
                            *(float4*)(sm.OUT + r * STF + c8 + 4) = o1;
                        }
                    }
                }
                // Z low cols (input part) are already correct from gate Z build
            }
            __syncthreads();

            // ============ CANDIDATE dconv + fused GRU update ============
            {
                u64 ca[18];
#pragma unroll
                for (int q = 0; q < 18; q++) ca[q] = 0;
#pragma unroll 1
                for (int m = 0; m < 5; m++) {
                    const float* feat;
                    if (m == 0) feat = sm.Z;
                    else {
                        int s = (m - 1) >> 1;
                        int second = (m - 1) & 1;
                        const float* src = second ? sm.Da : sm.Z;
                        float* dst = second ? sm.Db : sm.Da;
                        spmm4(sm.St2[s], src, dst,
                              second ? sm.Z : (const float*)0,
                              CC, rbase_s, bloc_s, nlo_s, c0_s);
                        __syncthreads();
                        feat = dst;
                    }
                    if (cell) gemm_cand<128>(feat, WC + (size_t)m * 128 * 64,
                                             kbeg, c4, rbase, ca);
                    else      gemm_cand<96> (feat, WC + (size_t)m * 96 * 64,
                                             kbeg, c4, rbase, ca);
                }
                __syncthreads();
                if (khalf) {
                    u64* s = scr + (size_t)(tid - 64) * 18;
#pragma unroll
                    for (int q = 0; q < 18; q++) s[q] = ca[q];
                }
                __syncthreads();
                if (!khalf) {
                    const u64* s = scr + (size_t)tid * 18;
#pragma unroll
                    for (int q = 0; q < 18; q++) add2(ca[q], s[q]);
                    float4 bv = *(const float4*)(BC + c4);
#pragma unroll
                    for (int i = 0; i < 9; i++) {
                        int r = rbase + i;
                        float2 q0 = up2(ca[2 * i]), q1 = up2(ca[2 * i + 1]);
                        float4 cc4 = make_float4(tanh_(q0.x + bv.x), tanh_(q0.y + bv.y),
                                                 tanh_(q1.x + bv.z), tanh_(q1.y + bv.w));
                        float4 uu = *(const float4*)(sm.OUT + r * STF + HIDN + c4);
                        float4 hh = *(const float4*)(H + r * STH + c4);
                        float4 nh = make_float4(cc4.x + uu.x * (hh.x - cc4.x),
                                                cc4.y + uu.y * (hh.y - cc4.y),
                                                cc4.z + uu.z * (hh.z - cc4.z),
                                                cc4.w + uu.w * (hh.w - cc4.w));
                        *(float4*)(H + r * STH + c4) = nh;
                    }
                }
            }
            __syncthreads();
        } // cell
    } // t

    // ---- epilogue: logits = relu(hB) @ fc_w + fc_b; out[b] = max over nodes ----
    if (tid < RB) {
        float acc = fcb[0];
#pragma unroll
        for (int c = 0; c < HIDN; c++)
            acc += fmaxf(sm.hB[tid * STH + c], 0.f) * fcw[c];
        sm.Da[tid] = acc;
    }
    __syncthreads();
    if (tid < NB) {
        float mx = -3.4e38f;
#pragma unroll
        for (int n = 0; n < NNODE; n++)
            mx = fmaxf(mx, sm.Da[tid * NNODE + n]);
        out[bbase + tid] = mx;
    }
}

extern "C" void kernel_launch(void* const* d_in, const int* in_sizes, int n_in,
                              void* d_out, int out_size)
{
    (void)in_sizes; (void)n_in; (void)out_size;
    const size_t shbytes = sizeof(Smem);
    cudaFuncSetAttribute(dcrnn_kernel,
                         cudaFuncAttributeMaxDynamicSharedMemorySize,
                         (int)shbytes);
    dcrnn_kernel<<<NBLK, THREADS, shbytes>>>(
        (const float*)d_in[0],  (const float*)d_in[1],
        (const float*)d_in[2],  (const float*)d_in[3],
        (const float*)d_in[4],  (const float*)d_in[5],
        (const float*)d_in[6],  (const float*)d_in[7],
        (const float*)d_in[8],  (const float*)d_in[9],
        (const float*)d_in[10], (const float*)d_in[11],
        (float*)d_out);
}

// round 15
// speedup vs baseline: 1.3182x; 1.3182x over previous
#include <cuda_runtime.h>
#include <cuda_bf16.h>

#define NB      4
#define RB      72
#define RBP     80          // padded rows for m16 tiles
#define THREADS 256
#define TSTEPS  128
#define NNODE   18
#define DIMX    32
#define HIDN    64
#define STB     136         // bf16 feat row stride (elements)
#define STH     68          // fp32 h/OUT row stride
#define NBLK    128
#define STS2    24

typedef unsigned long long u64;
typedef unsigned int uint;
typedef unsigned short ushort;

// ---------------- packed weights: bf16 hi/lo, transposed [n][kg] ----------
__device__ ushort g_wg0h[128 * 480], g_wg0l[128 * 480];
__device__ ushort g_wc0h[64 * 480],  g_wc0l[64 * 480];
__device__ ushort g_wg1h[128 * 640], g_wg1l[128 * 640];
__device__ ushort g_wc1h[64 * 640],  g_wc1l[64 * 640];

// ---------------- helpers ----------------
__device__ __forceinline__ u64 pk2(float a, float b) {
    u64 r;
    asm("mov.b64 %0, {%1, %2};" : "=l"(r)
        : "r"(__float_as_uint(a)), "r"(__float_as_uint(b)));
    return r;
}
__device__ __forceinline__ float2 up2(u64 v) {
    unsigned lo, hi;
    asm("mov.b64 {%0, %1}, %2;" : "=r"(lo), "=r"(hi) : "l"(v));
    return make_float2(__uint_as_float(lo), __uint_as_float(hi));
}
__device__ __forceinline__ void fma2(u64 &d, u64 a, u64 b) {
    asm("fma.rn.f32x2 %0, %1, %2, %0;" : "+l"(d) : "l"(a), "l"(b));
}
__device__ __forceinline__ float ex2f(float x) {
    float r; asm("ex2.approx.ftz.f32 %0, %1;" : "=f"(r) : "f"(x)); return r;
}
__device__ __forceinline__ float rcpf(float x) {
    float r; asm("rcp.approx.ftz.f32 %0, %1;" : "=f"(r) : "f"(x)); return r;
}
__device__ __forceinline__ float sigm(float v) {
    return rcpf(1.f + ex2f(-1.4426950408889634f * v));
}
__device__ __forceinline__ float tanh_(float v) {
    return 1.f - 2.f * rcpf(1.f + ex2f(2.8853900817779268f * v));
}
// pack two floats into bf16x2 (x -> low half, y -> high half)
__device__ __forceinline__ uint bfpack(float x, float y) {
    uint r;
    asm("cvt.rn.bf16x2.f32 %0, %1, %2;" : "=r"(r) : "f"(y), "f"(x));
    return r;
}
__device__ __forceinline__ float bflo(uint u) { return __uint_as_float(u << 16); }
__device__ __forceinline__ float bfhi(uint u) { return __uint_as_float(u & 0xffff0000u); }

// hi/lo split of a float pair -> (hi bf16x2, lo bf16x2)
__device__ __forceinline__ void split2(float x, float y, uint &h, uint &l) {
    h = bfpack(x, y);
    l = bfpack(x - bflo(h), y - bfhi(h));
}

// m16n8k16 bf16 mma, fp32 accumulate
__device__ __forceinline__ void mma16816(float* d, uint a0, uint a1, uint a2, uint a3,
                                         uint b0, uint b1) {
    asm volatile(
        "mma.sync.aligned.m16n8k16.row.col.f32.bf16.bf16.f32 "
        "{%0,%1,%2,%3},{%4,%5,%6,%7},{%8,%9},{%0,%1,%2,%3};"
        : "+f"(d[0]), "+f"(d[1]), "+f"(d[2]), "+f"(d[3])
        : "r"(a0), "r"(a1), "r"(a2), "r"(a3), "r"(b0), "r"(b1));
}

// ---------------- weight pack kernel: fp32 -> bf16 hi/lo, [n][kg] ----------
__global__ void pack_kernel(const float* __restrict__ wg0, const float* __restrict__ wc0,
                            const float* __restrict__ wg1, const float* __restrict__ wc1)
{
    int i = blockIdx.x * 256 + threadIdx.x;
    float v; ushort *ph, *pl; int off;
    if (i < 61440)       { int n = i / 480, k = i % 480; v = wg0[k * 128 + n];
                           ph = g_wg0h; pl = g_wg0l; off = i; }
    else if (i < 92160)  { int j = i - 61440; int n = j / 480, k = j % 480;
                           v = wc0[k * 64 + n]; ph = g_wc0h; pl = g_wc0l; off = j; }
    else if (i < 174080) { int j = i - 92160; int n = j / 640, k = j % 640;
                           v = wg1[k * 128 + n]; ph = g_wg1h; pl = g_wg1l; off = j; }
    else if (i < 215040) { int j = i - 174080; int n = j / 640, k = j % 640;
                           v = wc1[k * 64 + n]; ph = g_wc1h; pl = g_wc1l; off = j; }
    else return;
    __nv_bfloat16 h = __float2bfloat16(v);
    float lo = v - __bfloat162float(h);
    __nv_bfloat16 l = __float2bfloat16(lo);
    ph[off] = __bfloat16_as_ushort(h);
    pl[off] = __bfloat16_as_ushort(l);
}

// ---------------- shared memory ----------------
struct __align__(16) Smem {
    float2 St2[2][NNODE * STS2];       // transposed supports (dup pairs)
    float hA[RB * STH];
    float hB[RB * STH];
    float U[RB * STH];                 // gate u output; logits scratch at end
    ushort Zh[RBP * STB], Zl[RBP * STB];
    ushort Dah[RBP * STB], Dal[RBP * STB];
    ushort Dbh[RBP * STB], Dbl[RBP * STB];
};
// ~196 KB -> 1 CTA/SM

// ---------------- spmm (bf16 hi/lo IO, fp32 math) ----------------
__device__ __forceinline__ void spmm4(const float2* __restrict__ St,
                                      const ushort* __restrict__ srch,
                                      const ushort* __restrict__ srcl,
                                      ushort* __restrict__ dsth,
                                      ushort* __restrict__ dstl,
                                      const ushort* __restrict__ zsubh,
                                      const ushort* __restrict__ zsubl,
                                      int CC, int rbase, int bloc, int nlo, int c0)
{
    if (c0 >= CC) return;
    const int sb = bloc * NNODE * STB + c0;
    u64 a[18];
#pragma unroll
    for (int i = 0; i < 18; i++) a[i] = 0;
    uint2 Hc = *(const uint2*)(srch + sb);
    uint2 Lc = *(const uint2*)(srcl + sb);
#pragma unroll 1
    for (int mm = 0; mm < NNODE; mm++) {
        uint2 hc = Hc, lc = Lc;
        if (mm + 1 < NNODE) {
            Hc = *(const uint2*)(srch + sb + (mm + 1) * STB);
            Lc = *(const uint2*)(srcl + sb + (mm + 1) * STB);
        }
        float f0 = bflo(hc.x) + bflo(lc.x), f1 = bfhi(hc.x) + bfhi(lc.x);
        float f2 = bflo(hc.y) + bflo(lc.y), f3 = bfhi(hc.y) + bfhi(lc.y);
        u64 z1 = pk2(f0, f1), z2 = pk2(f2, f3);
        const float2* sp = St + mm * STS2 + nlo;
        ulonglong2 p01 = *(const ulonglong2*)(sp);
        ulonglong2 p23 = *(const ulonglong2*)(sp + 2);
        ulonglong2 p45 = *(const ulonglong2*)(sp + 4);
        ulonglong2 p67 = *(const ulonglong2*)(sp + 6);
        u64        p8  = *(const u64*)(sp + 8);
        fma2(a[0],  p01.x, z1); fma2(a[1],  p01.x, z2);
        fma2(a[2],  p01.y, z1); fma2(a[3],  p01.y, z2);
        fma2(a[4],  p23.x, z1); fma2(a[5],  p23.x, z2);
        fma2(a[6],  p23.y, z1); fma2(a[7],  p23.y, z2);
        fma2(a[8],  p45.x, z1); fma2(a[9],  p45.x, z2);
        fma2(a[10], p45.y, z1); fma2(a[11], p45.y, z2);
        fma2(a[12], p67.x, z1); fma2(a[13], p67.x, z2);
        fma2(a[14], p8,    z1); fma2(a[15], p8,    z2);
        // note: row pattern is 9 rows -> a[16],a[17] for row 8
        fma2(a[16], p67.y, z1); fma2(a[17], p67.y, z2);
    }
#pragma unroll
    for (int i = 0; i < 9; i++) {
        // accumulator index mapping: rows 0..6 at a[2i], row7 uses a[16](p67.y),
        // row8 uses a[14](p8). Fix mapping: reorder below.
        int ai;
        if (i < 7)      ai = 2 * i;
        else if (i == 7) ai = 16;   // p67.y
        else             ai = 14;   // p8
        float2 q0 = up2(a[ai]), q1 = up2(a[ai + 1]);
        float v0 = q0.x, v1 = q0.y, v2 = q1.x, v3 = q1.y;
        int idx = (rbase + i) * STB + c0;
        if (zsubh) {
            uint2 zh = *(const uint2*)(zsubh + idx);
            uint2 zl = *(const uint2*)(zsubl + idx);
            v0 = 2.f * v0 - (bflo(zh.x) + bflo(zl.x));
            v1 = 2.f * v1 - (bfhi(zh.x) + bfhi(zl.x));
            v2 = 2.f * v2 - (bflo(zh.y) + bflo(zl.y));
            v3 = 2.f * v3 - (bfhi(zh.y) + bfhi(zl.y));
        }
        uint h0, l0, h1, l1;
        split2(v0, v1, h0, l0);
        split2(v2, v3, h1, l1);
        *(uint2*)(dsth + idx) = make_uint2(h0, h1);
        *(uint2*)(dstl + idx) = make_uint2(l0, l1);
    }
}

// ---------------- gate GEMM: warp owns 2 n8-tiles, full M (5 m16), full K ----
template<int CC>
__device__ __forceinline__ void gemm_gate_mma(const ushort* __restrict__ fh,
                                              const ushort* __restrict__ fl,
                                              const ushort* __restrict__ wth,
                                              const ushort* __restrict__ wtl,
                                              int Kt, int kgbase, int nb,
                                              int lr, int lc, float* dg)
{
    constexpr int KS = CC / 16;
    const ushort* bph = wth + (size_t)(nb + lr) * Kt + kgbase + 2 * lc;
    const ushort* bpl = wtl + (size_t)(nb + lr) * Kt + kgbase + 2 * lc;
    const ushort* fah = fh + lr * STB + 2 * lc;
    const ushort* fal = fl + lr * STB + 2 * lc;
    uint bh[2][2], bl[2][2];
#pragma unroll
    for (int j = 0; j < 2; j++) {
        const ushort* p = bph + j * 8 * Kt;
        const ushort* q = bpl + j * 8 * Kt;
        bh[j][0] = __ldg((const uint*)p); bh[j][1] = __ldg((const uint*)(p + 8));
        bl[j][0] = __ldg((const uint*)q); bl[j][1] = __ldg((const uint*)(q + 8));
    }
#pragma unroll 1
    for (int ks = 0; ks < KS; ks++) {
        uint ah[5][4], al[5][4];
#pragma unroll
        for (int mt = 0; mt < 5; mt++) {
            const ushort* p = fah + mt * 16 * STB + ks * 16;
            ah[mt][0] = *(const uint*)p;
            ah[mt][1] = *(const uint*)(p + 8 * STB);
            ah[mt][2] = *(const uint*)(p + 8);
            ah[mt][3] = *(const uint*)(p + 8 * STB + 8);
            const ushort* q = fal + mt * 16 * STB + ks * 16;
            al[mt][0] = *(const uint*)q;
            al[mt][1] = *(const uint*)(q + 8 * STB);
            al[mt][2] = *(const uint*)(q + 8);
            al[mt][3] = *(const uint*)(q + 8 * STB + 8);
        }
        uint nh[2][2], nl[2][2];
        if (ks + 1 < KS) {
#pragma unroll
            for (int j = 0; j < 2; j++) {
                const ushort* p = bph + j * 8 * Kt + (ks + 1) * 16;
                const ushort* q = bpl + j * 8 * Kt + (ks + 1) * 16;
                nh[j][0] = __ldg((const uint*)p); nh[j][1] = __ldg((const uint*)(p + 8));
                nl[j][0] = __ldg((const uint*)q); nl[j][1] = __ldg((const uint*)(q + 8));
            }
        }
#pragma unroll
        for (int j = 0; j < 2; j++)
#pragma unroll
            for (int mt = 0; mt < 5; mt++) {
                float* d = dg + (j * 5 + mt) * 4;
                mma16816(d, ah[mt][0], ah[mt][1], ah[mt][2], ah[mt][3], bh[j][0], bh[j][1]);
                mma16816(d, al[mt][0], al[mt][1], al[mt][2], al[mt][3], bh[j][0], bh[j][1]);
                mma16816(d, ah[mt][0], ah[mt][1], ah[mt][2], ah[mt][3], bl[j][0], bl[j][1]);
            }
        if (ks + 1 < KS) {
#pragma unroll
            for (int j = 0; j < 2; j++) {
                bh[j][0] = nh[j][0]; bh[j][1] = nh[j][1];
                bl[j][0] = nl[j][0]; bl[j][1] = nl[j][1];
            }
        }
    }
}

// ---------------- cand GEMM: warp owns 1 n8-tile ----------------
template<int CC>
__device__ __forceinline__ void gemm_cand_mma(const ushort* __restrict__ fh,
                                              const ushort* __restrict__ fl,
                                              const ushort* __restrict__ wth,
                                              const ushort* __restrict__ wtl,
                                              int Kt, int kgbase, int nb,
                                              int lr, int lc, float* dc)
{
    constexpr int KS = CC / 16;
    const ushort* bph = wth + (size_t)(nb + lr) * Kt + kgbase + 2 * lc;
    const ushort* bpl = wtl + (size_t)(nb + lr) * Kt + kgbase + 2 * lc;
    const ushort* fah = fh + lr * STB + 2 * lc;
    const ushort* fal = fl + lr * STB + 2 * lc;
    uint b0h = __ldg((const uint*)bph), b1h = __ldg((const uint*)(bph + 8));
    uint b0l = __ldg((const uint*)bpl), b1l = __ldg((const uint*)(bpl + 8));
#pragma unroll 1
    for (int ks = 0; ks < KS; ks++) {
        uint ah[5][4], al[5][4];
#pragma unroll
        for (int mt = 0; mt < 5; mt++) {
            const ushort* p = fah + mt * 16 * STB + ks * 16;
            ah[mt][0] = *(const uint*)p;
            ah[mt][1] = *(const uint*)(p + 8 * STB);
            ah[mt][2] = *(const uint*)(p + 8);
            ah[mt][3] = *(const uint*)(p + 8 * STB + 8);
            const ushort* q = fal + mt * 16 * STB + ks * 16;
            al[mt][0] = *(const uint*)q;
            al[mt][1] = *(const uint*)(q + 8 * STB);
            al[mt][2] = *(const uint*)(q + 8);
            al[mt][3] = *(const uint*)(q + 8 * STB + 8);
        }
        uint n0h = 0, n1h = 0, n0l = 0, n1l = 0;
        if (ks + 1 < KS) {
            n0h = __ldg((const uint*)(bph + (ks + 1) * 16));
            n1h = __ldg((const uint*)(bph + (ks + 1) * 16 + 8));
            n0l = __ldg((const uint*)(bpl + (ks + 1) * 16));
            n1l = __ldg((const uint*)(bpl + (ks + 1) * 16 + 8));
        }
#pragma unroll
        for (int mt = 0; mt < 5; mt++) {
            float* d = dc + mt * 4;
            mma16816(d, ah[mt][0], ah[mt][1], ah[mt][2], ah[mt][3], b0h, b1h);
            mma16816(d, al[mt][0], al[mt][1], al[mt][2], al[mt][3], b0h, b1h);
            mma16816(d, ah[mt][0], ah[mt][1], ah[mt][2], ah[mt][3], b0l, b1l);
        }
        if (ks + 1 < KS) { b0h = n0h; b1h = n1h; b0l = n0l; b1l = n1l; }
    }
}

// ---------------- main persistent kernel ----------------
__global__ void __launch_bounds__(THREADS, 1)
dcrnn_kernel(const float* __restrict__ x,   const float* __restrict__ sup,
             const float* __restrict__ bg0, const float* __restrict__ bc0,
             const float* __restrict__ bg1, const float* __restrict__ bc1,
             const float* __restrict__ fcw, const float* __restrict__ fcb,
             float* __restrict__ out)
{
    extern __shared__ char smraw[];
    Smem& sm = *reinterpret_cast<Smem*>(smraw);

    const int tid   = threadIdx.x;
    const int bbase = blockIdx.x * NB;
    const int w     = tid >> 5;
    const int lane  = tid & 31;
    const int lr    = lane >> 2;
    const int lc    = lane & 3;
    // spmm map (R12)
    const int rowg_s  = tid & 7;
    const int c0_s    = 4 * ((tid >> 3) & 15) + 64 * (tid >> 7);
    const int rbase_s = 9 * rowg_s;
    const int bloc_s  = rowg_s >> 1;
    const int nlo_s   = (rowg_s & 1) ? 12 : 0;

    // init supports (transposed, duplicated pairs)
    for (int i = tid; i < 2 * NNODE * NNODE; i += THREADS) {
        int s = i / (NNODE * NNODE);
        int rem = i - s * NNODE * NNODE;
        int n = rem / NNODE;
        int m = rem - n * NNODE;
        float v = sup[i];
        int ln = (n < 9) ? n : (12 + n - 9);
        sm.St2[s][m * STS2 + ln] = make_float2(v, v);
    }
    for (int i = tid; i < RB * STH; i += THREADS) {
        sm.hA[i] = 0.f; sm.hB[i] = 0.f; sm.U[i] = 0.f;
    }
    // zero all 6 bf16 buffers (contiguous)
    for (int i = tid; i < 6 * RBP * STB / 2; i += THREADS)
        ((uint*)sm.Zh)[i] = 0;
    __syncthreads();

    for (int t = 0; t < TSTEPS; t++) {
        for (int cell = 0; cell < 2; cell++) {
            const int CC   = cell ? 128 : 96;
            const int hoff = cell ? HIDN : DIMX;
            const int Kt   = cell ? 640 : 480;
            const float* BG = cell ? bg1 : bg0;
            const float* BC = cell ? bc1 : bc0;
            float* H = cell ? sm.hB : sm.hA;
            const ushort* WGH = cell ? g_wg1h : g_wg0h;
            const ushort* WGL = cell ? g_wg1l : g_wg0l;
            const ushort* WCH = cell ? g_wc1h : g_wc0h;
            const ushort* WCL = cell ? g_wc1l : g_wc0l;

            // ===== gate Z build: Zh/Zl = split([input | H_prev]) =====
            if (cell == 0) {
                for (int j = tid; j < RB * 24; j += THREADS) {
                    int r = j / 24, c = 4 * (j - 24 * r);
                    float4 v;
                    if (c < DIMX) {
                        int b = bbase + r / NNODE;
                        int n = r - NNODE * (r / NNODE);
                        v = *(const float4*)(x +
                            (((size_t)b * TSTEPS + t) * NNODE + n) * DIMX + c);
                    } else {
                        v = *(const float4*)(sm.hA + r * STH + (c - DIMX));
                    }
                    uint h0, l0, h1, l1;
                    split2(v.x, v.y, h0, l0);
                    split2(v.z, v.w, h1, l1);
                    int idx = r * STB + c;
                    *(uint2*)(sm.Zh + idx) = make_uint2(h0, h1);
                    *(uint2*)(sm.Zl + idx) = make_uint2(l0, l1);
                }
            } else {
                for (int j = tid; j < RB * 32; j += THREADS) {
                    int r = j >> 5, c = 4 * (j & 31);
                    float4 v = (c < HIDN)
                        ? *(const float4*)(sm.hA + r * STH + c)
                        : *(const float4*)(sm.hB + r * STH + (c - HIDN));
                    uint h0, l0, h1, l1;
                    split2(v.x, v.y, h0, l0);
                    split2(v.z, v.w, h1, l1);
                    int idx = r * STB + c;
                    *(uint2*)(sm.Zh + idx) = make_uint2(h0, h1);
                    *(uint2*)(sm.Zl + idx) = make_uint2(l0, l1);
                }
            }
            __syncthreads();

            // ===== GATE dconv (tensor) =====
            {
                float dg[40];
#pragma unroll
                for (int q = 0; q < 40; q++) dg[q] = 0.f;
#pragma unroll 1
                for (int m = 0; m < 5; m++) {
                    const ushort *fh, *fl;
                    if (m == 0) { fh = sm.Zh; fl = sm.Zl; }
                    else {
                        int s = (m - 1) >> 1;
                        int second = (m - 1) & 1;
                        const ushort* srch = second ? sm.Dah : sm.Zh;
                        const ushort* srcl = second ? sm.Dal : sm.Zl;
                        ushort* dsth = second ? sm.Dbh : sm.Dah;
                        ushort* dstl = second ? sm.Dbl : sm.Dal;
                        spmm4(sm.St2[s], srch, srcl, dsth, dstl,
                              second ? sm.Zh : (const ushort*)0,
                              second ? sm.Zl : (const ushort*)0,
                              CC, rbase_s, bloc_s, nlo_s, c0_s);
                        __syncthreads();
                        fh = dsth; fl = dstl;
                    }
                    if (cell) gemm_gate_mma<128>(fh, fl, WGH, WGL, Kt, m * 128,
                                                 16 * w, lr, lc, dg);
                    else      gemm_gate_mma<96> (fh, fl, WGH, WGL, Kt, m * 96,
                                                 16 * w, lr, lc, dg);
                }
                // writeout: r-part into Zh/Zl (warps 0-3), u-part into U (4-7)
#pragma unroll
                for (int j = 0; j < 2; j++) {
                    int cb = 16 * w + 8 * j + 2 * lc;
                    float2 bv = *(const float2*)(BG + cb);
#pragma unroll
                    for (int mt = 0; mt < 5; mt++) {
                        float* d = dg + (j * 5 + mt) * 4;
                        int r0 = mt * 16 + lr, r1 = r0 + 8;
                        if (cb < HIDN) {
                            float2 h0 = *(const float2*)(H + r0 * STH + cb);
                            float v0 = sigm(d[0] + bv.x) * h0.x;
                            float v1 = sigm(d[1] + bv.y) * h0.y;
                            uint hh, ll;
                            split2(v0, v1, hh, ll);
                            *(uint*)(sm.Zh + r0 * STB + hoff + cb) = hh;
                            *(uint*)(sm.Zl + r0 * STB + hoff + cb) = ll;
                            if (mt < 4) {
                                float2 h1 = *(const float2*)(H + r1 * STH + cb);
                                float v2 = sigm(d[2] + bv.x) * h1.x;
                                float v3 = sigm(d[3] + bv.y) * h1.y;
                                split2(v2, v3, hh, ll);
                                *(uint*)(sm.Zh + r1 * STB + hoff + cb) = hh;
                                *(uint*)(sm.Zl + r1 * STB + hoff + cb) = ll;
                            }
                        } else {
                            int cu = cb - HIDN;
                            *(float2*)(sm.U + r0 * STH + cu) =
                                make_float2(sigm(d[0] + bv.x), sigm(d[1] + bv.y));
                            if (mt < 4)
                                *(float2*)(sm.U + r1 * STH + cu) =
                                    make_float2(sigm(d[2] + bv.x), sigm(d[3] + bv.y));
                        }
                    }
                }
            }
            __syncthreads();

            // ===== CANDIDATE dconv (tensor) + fused GRU update =====
            {
                float dc[20];
#pragma unroll
                for (int q = 0; q < 20; q++) dc[q] = 0.f;
#pragma unroll 1
                for (int m = 0; m < 5; m++) {
                    const ushort *fh, *fl;
                    if (m == 0) { fh = sm.Zh; fl = sm.Zl; }
                    else {
                        int s = (m - 1) >> 1;
                        int second = (m - 1) & 1;
                        const ushort* srch = second ? sm.Dah : sm.Zh;
                        const ushort* srcl = second ? sm.Dal : sm.Zl;
                        ushort* dsth = second ? sm.Dbh : sm.Dah;
                        ushort* dstl = second ? sm.Dbl : sm.Dal;
                        spmm4(sm.St2[s], srch, srcl, dsth, dstl,
                              second ? sm.Zh : (const ushort*)0,
                              second ? sm.Zl : (const ushort*)0,
                              CC, rbase_s, bloc_s, nlo_s, c0_s);
                        __syncthreads();
                        fh = dsth; fl = dstl;
                    }
                    if (cell) gemm_cand_mma<128>(fh, fl, WCH, WCL, Kt, m * 128,
                                                 8 * w, lr, lc, dc);
                    else      gemm_cand_mma<96> (fh, fl, WCH, WCL, Kt, m * 96,
                                                 8 * w, lr, lc, dc);
                }
                // writeout: h = c + u*(h - c)
                {
                    int cb = 8 * w + 2 * lc;
                    float2 bv = *(const float2*)(BC + cb);
#pragma unroll
                    for (int mt = 0; mt < 5; mt++) {
                        float* d = dc + mt * 4;
                        int r0 = mt * 16 + lr, r1 = r0 + 8;
                        {
                            float c0v = tanh_(d[0] + bv.x), c1v = tanh_(d[1] + bv.y);
                            float2 u0 = *(const float2*)(sm.U + r0 * STH + cb);
                            float2 h0 = *(const float2*)(H + r0 * STH + cb);
                            *(float2*)(H + r0 * STH + cb) =
                                make_float2(c0v + u0.x * (h0.x - c0v),
                                            c1v + u0.y * (h0.y - c1v));
                        }
                        if (mt < 4) {
                            float c2v = tanh_(d[2] + bv.x), c3v = tanh_(d[3] + bv.y);
                            float2 u1 = *(const float2*)(sm.U + r1 * STH + cb);
                            float2 h1 = *(const float2*)(H + r1 * STH + cb);
                            *(float2*)(H + r1 * STH + cb) =
                                make_float2(c2v + u1.x * (h1.x - c2v),
                                            c3v + u1.y * (h1.y - c3v));
                        }
                    }
                }
            }
            __syncthreads();
        } // cell
    } // t

    // ---- epilogue: logits = relu(hB) @ fc_w + fc_b; out[b] = max over nodes ----
    if (tid < RB) {
        float acc = fcb[0];
#pragma unroll
        for (int c = 0; c < HIDN; c++)
            acc += fmaxf(sm.hB[tid * STH + c], 0.f) * fcw[c];
        sm.U[tid] = acc;
    }
    __syncthreads();
    if (tid < NB) {
        float mx = -3.4e38f;
#pragma unroll
        for (int n = 0; n < NNODE; n++)
            mx = fmaxf(mx, sm.U[tid * NNODE + n]);
        out[bbase + tid] = mx;
    }
}

extern "C" void kernel_launch(void* const* d_in, const int* in_sizes, int n_in,
                              void* d_out, int out_size)
{
    (void)in_sizes; (void)n_in; (void)out_size;
    const size_t shbytes = sizeof(Smem);
    cudaFuncSetAttribute(dcrnn_kernel,
                         cudaFuncAttributeMaxDynamicSharedMemorySize,
                         (int)shbytes);
    pack_kernel<<<(215040 + 255) / 256, 256>>>(
        (const float*)d_in[2], (const float*)d_in[4],
        (const float*)d_in[6], (const float*)d_in[8]);
    dcrnn_kernel<<<NBLK, THREADS, shbytes>>>(
        (const float*)d_in[0],  (const float*)d_in[1],
        (const float*)d_in[3],  (const float*)d_in[5],
        (const float*)d_in[7],  (const float*)d_in[9],
        (const float*)d_in[10], (const float*)d_in[11],
        (float*)d_out);
}

// round 16
// speedup vs baseline: 1.4001x; 1.0622x over previous
#include <cuda_runtime.h>
#include <cuda_bf16.h>

#define NB      4
#define RB      72
#define RBP     80          // padded rows for m16 tiles
#define THREADS 256
#define TSTEPS  128
#define NNODE   18
#define DIMX    32
#define HIDN    64
#define STB     136         // bf16 feat row stride (elements)
#define STH     68          // fp32 h/OUT row stride
#define NBLK    128
#define STS2    24

typedef unsigned long long u64;
typedef unsigned int uint;
typedef unsigned short ushort;

// ---------------- packed weights: bf16 hi/lo, transposed [n][kg] ----------
__device__ ushort g_wg0h[128 * 480], g_wg0l[128 * 480];
__device__ ushort g_wc0h[64 * 480],  g_wc0l[64 * 480];
__device__ ushort g_wg1h[128 * 640], g_wg1l[128 * 640];
__device__ ushort g_wc1h[64 * 640],  g_wc1l[64 * 640];

// ---------------- helpers ----------------
__device__ __forceinline__ u64 pk2(float a, float b) {
    u64 r;
    asm("mov.b64 %0, {%1, %2};" : "=l"(r)
        : "r"(__float_as_uint(a)), "r"(__float_as_uint(b)));
    return r;
}
__device__ __forceinline__ float2 up2(u64 v) {
    unsigned lo, hi;
    asm("mov.b64 {%0, %1}, %2;" : "=r"(lo), "=r"(hi) : "l"(v));
    return make_float2(__uint_as_float(lo), __uint_as_float(hi));
}
__device__ __forceinline__ void fma2(u64 &d, u64 a, u64 b) {
    asm("fma.rn.f32x2 %0, %1, %2, %0;" : "+l"(d) : "l"(a), "l"(b));
}
__device__ __forceinline__ float ex2f(float x) {
    float r; asm("ex2.approx.ftz.f32 %0, %1;" : "=f"(r) : "f"(x)); return r;
}
__device__ __forceinline__ float rcpf(float x) {
    float r; asm("rcp.approx.ftz.f32 %0, %1;" : "=f"(r) : "f"(x)); return r;
}
__device__ __forceinline__ float sigm(float v) {
    return rcpf(1.f + ex2f(-1.4426950408889634f * v));
}
__device__ __forceinline__ float tanh_(float v) {
    return 1.f - 2.f * rcpf(1.f + ex2f(2.8853900817779268f * v));
}
__device__ __forceinline__ uint bfpack(float x, float y) {
    uint r;
    asm("cvt.rn.bf16x2.f32 %0, %1, %2;" : "=r"(r) : "f"(y), "f"(x));
    return r;
}
__device__ __forceinline__ float bflo(uint u) { return __uint_as_float(u << 16); }
__device__ __forceinline__ float bfhi(uint u) { return __uint_as_float(u & 0xffff0000u); }
__device__ __forceinline__ void split2(float x, float y, uint &h, uint &l) {
    h = bfpack(x, y);
    l = bfpack(x - bflo(h), y - bfhi(h));
}
__device__ __forceinline__ uint s2u(const void* p) {
    uint a;
    asm("{ .reg .u64 t; cvta.to.shared.u64 t, %1; cvt.u32.u64 %0, t; }"
        : "=r"(a) : "l"(p));
    return a;
}

// m16n8k16 bf16 mma, fp32 accumulate
__device__ __forceinline__ void mma16816(float* d, const uint* a, uint b0, uint b1) {
    asm volatile(
        "mma.sync.aligned.m16n8k16.row.col.f32.bf16.bf16.f32 "
        "{%0,%1,%2,%3},{%4,%5,%6,%7},{%8,%9},{%0,%1,%2,%3};"
        : "+f"(d[0]), "+f"(d[1]), "+f"(d[2]), "+f"(d[3])
        : "r"(a[0]), "r"(a[1]), "r"(a[2]), "r"(a[3]), "r"(b0), "r"(b1));
}

// ldmatrix x4: one instruction loads the full m16k16 A fragment
__device__ __forceinline__ void ldsm4(uint* r, uint saddr) {
    asm volatile("ldmatrix.sync.aligned.m8n8.x4.shared.b16 {%0,%1,%2,%3}, [%4];"
        : "=r"(r[0]), "=r"(r[1]), "=r"(r[2]), "=r"(r[3]) : "r"(saddr));
}

// ---------------- weight pack kernel ----------------
__global__ void pack_kernel(const float* __restrict__ wg0, const float* __restrict__ wc0,
                            const float* __restrict__ wg1, const float* __restrict__ wc1)
{
    int i = blockIdx.x * 256 + threadIdx.x;
    float v; ushort *ph, *pl; int off;
    if (i < 61440)       { int n = i / 480, k = i % 480; v = wg0[k * 128 + n];
                           ph = g_wg0h; pl = g_wg0l; off = i; }
    else if (i < 92160)  { int j = i - 61440; int n = j / 480, k = j % 480;
                           v = wc0[k * 64 + n]; ph = g_wc0h; pl = g_wc0l; off = j; }
    else if (i < 174080) { int j = i - 92160; int n = j / 640, k = j % 640;
                           v = wg1[k * 128 + n]; ph = g_wg1h; pl = g_wg1l; off = j; }
    else if (i < 215040) { int j = i - 174080; int n = j / 640, k = j % 640;
                           v = wc1[k * 64 + n]; ph = g_wc1h; pl = g_wc1l; off = j; }
    else return;
    __nv_bfloat16 h = __float2bfloat16(v);
    float lo = v - __bfloat162float(h);
    __nv_bfloat16 l = __float2bfloat16(lo);
    ph[off] = __bfloat16_as_ushort(h);
    pl[off] = __bfloat16_as_ushort(l);
}

// ---------------- shared memory ----------------
struct __align__(16) Smem {
    float2 St2[2][NNODE * STS2];
    float hA[RB * STH];
    float hB[RB * STH];
    float U[RB * STH];
    ushort Zh[RBP * STB], Zl[RBP * STB];
    ushort Dah[RBP * STB], Dal[RBP * STB];
    ushort Dbh[RBP * STB], Dbl[RBP * STB];
};

// ---------------- spmm (bf16 hi/lo IO, fp32 math) ----------------
__device__ __forceinline__ void spmm4(const float2* __restrict__ St,
                                      const ushort* __restrict__ srch,
                                      const ushort* __restrict__ srcl,
                                      ushort* __restrict__ dsth,
                                      ushort* __restrict__ dstl,
                                      const ushort* __restrict__ zsubh,
                                      const ushort* __restrict__ zsubl,
                                      int CC, int rbase, int bloc, int nlo, int c0)
{
    if (c0 >= CC) return;
    const int sb = bloc * NNODE * STB + c0;
    u64 a[18];
#pragma unroll
    for (int i = 0; i < 18; i++) a[i] = 0;
    uint2 Hc = *(const uint2*)(srch + sb);
    uint2 Lc = *(const uint2*)(srcl + sb);
#pragma unroll 1
    for (int mm = 0; mm < NNODE; mm++) {
        uint2 hc = Hc, lc = Lc;
        if (mm + 1 < NNODE) {
            Hc = *(const uint2*)(srch + sb + (mm + 1) * STB);
            Lc = *(const uint2*)(srcl + sb + (mm + 1) * STB);
        }
        float f0 = bflo(hc.x) + bflo(lc.x), f1 = bfhi(hc.x) + bfhi(lc.x);
        float f2 = bflo(hc.y) + bflo(lc.y), f3 = bfhi(hc.y) + bfhi(lc.y);
        u64 z1 = pk2(f0, f1), z2 = pk2(f2, f3);
        const float2* sp = St + mm * STS2 + nlo;
        ulonglong2 p01 = *(const ulonglong2*)(sp);
        ulonglong2 p23 = *(const ulonglong2*)(sp + 2);
        ulonglong2 p45 = *(const ulonglong2*)(sp + 4);
        ulonglong2 p67 = *(const ulonglong2*)(sp + 6);
        u64        p8  = *(const u64*)(sp + 8);
        fma2(a[0],  p01.x, z1); fma2(a[1],  p01.x, z2);
        fma2(a[2],  p01.y, z1); fma2(a[3],  p01.y, z2);
        fma2(a[4],  p23.x, z1); fma2(a[5],  p23.x, z2);
        fma2(a[6],  p23.y, z1); fma2(a[7],  p23.y, z2);
        fma2(a[8],  p45.x, z1); fma2(a[9],  p45.x, z2);
        fma2(a[10], p45.y, z1); fma2(a[11], p45.y, z2);
        fma2(a[12], p67.x, z1); fma2(a[13], p67.x, z2);
        fma2(a[14], p8,    z1); fma2(a[15], p8,    z2);
        fma2(a[16], p67.y, z1); fma2(a[17], p67.y, z2);
    }
#pragma unroll
    for (int i = 0; i < 9; i++) {
        int ai;
        if (i < 7)      ai = 2 * i;
        else if (i == 7) ai = 16;   // p67.y
        else             ai = 14;   // p8
        float2 q0 = up2(a[ai]), q1 = up2(a[ai + 1]);
        float v0 = q0.x, v1 = q0.y, v2 = q1.x, v3 = q1.y;
        int idx = (rbase + i) * STB + c0;
        if (zsubh) {
            uint2 zh = *(const uint2*)(zsubh + idx);
            uint2 zl = *(const uint2*)(zsubl + idx);
            v0 = 2.f * v0 - (bflo(zh.x) + bflo(zl.x));
            v1 = 2.f * v1 - (bfhi(zh.x) + bfhi(zl.x));
            v2 = 2.f * v2 - (bflo(zh.y) + bflo(zl.y));
            v3 = 2.f * v3 - (bfhi(zh.y) + bfhi(zl.y));
        }
        uint h0, l0, h1, l1;
        split2(v0, v1, h0, l0);
        split2(v2, v3, h1, l1);
        *(uint2*)(dsth + idx) = make_uint2(h0, h1);
        *(uint2*)(dstl + idx) = make_uint2(l0, l1);
    }
}

// ---------------- gate GEMM: warp owns 2 n8-tiles, full M, full K ----------
// fhU/flU: u32 shared addr of feat base + per-lane ldmatrix offset
template<int CC>
__device__ __forceinline__ void gemm_gate_mma(uint fhU, uint flU,
                                              const ushort* __restrict__ wth,
                                              const ushort* __restrict__ wtl,
                                              int Kt, int kgbase, int nb,
                                              int lr, int lc, float* dg)
{
    constexpr int KS = CC / 16;
    const ushort* bph = wth + (size_t)(nb + lr) * Kt + kgbase + 2 * lc;
    const ushort* bpl = wtl + (size_t)(nb + lr) * Kt + kgbase + 2 * lc;
    uint bh[2][2], bl[2][2];
#pragma unroll
    for (int j = 0; j < 2; j++) {
        const ushort* p = bph + j * 8 * Kt;
        const ushort* q = bpl + j * 8 * Kt;
        bh[j][0] = __ldg((const uint*)p); bh[j][1] = __ldg((const uint*)(p + 8));
        bl[j][0] = __ldg((const uint*)q); bl[j][1] = __ldg((const uint*)(q + 8));
    }
#pragma unroll 1
    for (int ks = 0; ks < KS; ks++) {
        uint ah[5][4], al[5][4];
#pragma unroll
        for (int mt = 0; mt < 5; mt++) {
            uint off = (uint)((mt * 16 * STB + ks * 16) * 2);
            ldsm4(ah[mt], fhU + off);
            ldsm4(al[mt], flU + off);
        }
        uint nh[2][2], nl[2][2];
        if (ks + 1 < KS) {
#pragma unroll
            for (int j = 0; j < 2; j++) {
                const ushort* p = bph + j * 8 * Kt + (ks + 1) * 16;
                const ushort* q = bpl + j * 8 * Kt + (ks + 1) * 16;
                nh[j][0] = __ldg((const uint*)p); nh[j][1] = __ldg((const uint*)(p + 8));
                nl[j][0] = __ldg((const uint*)q); nl[j][1] = __ldg((const uint*)(q + 8));
            }
        }
#pragma unroll
        for (int j = 0; j < 2; j++)
#pragma unroll
            for (int mt = 0; mt < 5; mt++) {
                float* d = dg + (j * 5 + mt) * 4;
                mma16816(d, ah[mt], bh[j][0], bh[j][1]);
                mma16816(d, al[mt], bh[j][0], bh[j][1]);
                mma16816(d, ah[mt], bl[j][0], bl[j][1]);
            }
        if (ks + 1 < KS) {
#pragma unroll
            for (int j = 0; j < 2; j++) {
                bh[j][0] = nh[j][0]; bh[j][1] = nh[j][1];
                bl[j][0] = nl[j][0]; bl[j][1] = nl[j][1];
            }
        }
    }
}

// ---------------- cand GEMM: warp owns 1 n8-tile ----------------
template<int CC>
__device__ __forceinline__ void gemm_cand_mma(uint fhU, uint flU,
                                              const ushort* __restrict__ wth,
                                              const ushort* __restrict__ wtl,
                                              int Kt, int kgbase, int nb,
                                              int lr, int lc, float* dc)
{
    constexpr int KS = CC / 16;
    const ushort* bph = wth + (size_t)(nb + lr) * Kt + kgbase + 2 * lc;
    const ushort* bpl = wtl + (size_t)(nb + lr) * Kt + kgbase + 2 * lc;
    uint b0h = __ldg((const uint*)bph), b1h = __ldg((const uint*)(bph + 8));
    uint b0l = __ldg((const uint*)bpl), b1l = __ldg((const uint*)(bpl + 8));
#pragma unroll 1
    for (int ks = 0; ks < KS; ks++) {
        uint ah[5][4], al[5][4];
#pragma unroll
        for (int mt = 0; mt < 5; mt++) {
            uint off = (uint)((mt * 16 * STB + ks * 16) * 2);
            ldsm4(ah[mt], fhU + off);
            ldsm4(al[mt], flU + off);
        }
        uint n0h = 0, n1h = 0, n0l = 0, n1l = 0;
        if (ks + 1 < KS) {
            n0h = __ldg((const uint*)(bph + (ks + 1) * 16));
            n1h = __ldg((const uint*)(bph + (ks + 1) * 16 + 8));
            n0l = __ldg((const uint*)(bpl + (ks + 1) * 16));
            n1l = __ldg((const uint*)(bpl + (ks + 1) * 16 + 8));
        }
#pragma unroll
        for (int mt = 0; mt < 5; mt++) {
            float* d = dc + mt * 4;
            mma16816(d, ah[mt], b0h, b1h);
            mma16816(d, al[mt], b0h, b1h);
            mma16816(d, ah[mt], b0l, b1l);
        }
        if (ks + 1 < KS) { b0h = n0h; b1h = n1h; b0l = n0l; b1l = n1l; }
    }
}

// ---------------- main persistent kernel ----------------
__global__ void __launch_bounds__(THREADS, 1)
dcrnn_kernel(const float* __restrict__ x,   const float* __restrict__ sup,
             const float* __restrict__ bg0, const float* __restrict__ bc0,
             const float* __restrict__ bg1, const float* __restrict__ bc1,
             const float* __restrict__ fcw, const float* __restrict__ fcb,
             float* __restrict__ out)
{
    extern __shared__ char smraw[];
    Smem& sm = *reinterpret_cast<Smem*>(smraw);

    const int tid   = threadIdx.x;
    const int bbase = blockIdx.x * NB;
    const int w     = tid >> 5;
    const int lane  = tid & 31;
    const int lr    = lane >> 2;
    const int lc    = lane & 3;
    // ldmatrix per-lane offset: row (lane&15), k-half 8*(lane>>4)
    const uint lmoff = (uint)((((lane & 15) * STB) + 8 * (lane >> 4)) * 2);
    const uint ZhU  = s2u(sm.Zh)  + lmoff, ZlU  = s2u(sm.Zl)  + lmoff;
    const uint DahU = s2u(sm.Dah) + lmoff, DalU = s2u(sm.Dal) + lmoff;
    const uint DbhU = s2u(sm.Dbh) + lmoff, DblU = s2u(sm.Dbl) + lmoff;
    // spmm map (R12)
    const int rowg_s  = tid & 7;
    const int c0_s    = 4 * ((tid >> 3) & 15) + 64 * (tid >> 7);
    const int rbase_s = 9 * rowg_s;
    const int bloc_s  = rowg_s >> 1;
    const int nlo_s   = (rowg_s & 1) ? 12 : 0;

    for (int i = tid; i < 2 * NNODE * NNODE; i += THREADS) {
        int s = i / (NNODE * NNODE);
        int rem = i - s * NNODE * NNODE;
        int n = rem / NNODE;
        int m = rem - n * NNODE;
        float v = sup[i];
        int ln = (n < 9) ? n : (12 + n - 9);
        sm.St2[s][m * STS2 + ln] = make_float2(v, v);
    }
    for (int i = tid; i < RB * STH; i += THREADS) {
        sm.hA[i] = 0.f; sm.hB[i] = 0.f; sm.U[i] = 0.f;
    }
    for (int i = tid; i < 6 * RBP * STB / 2; i += THREADS)
        ((uint*)sm.Zh)[i] = 0;
    __syncthreads();

    for (int t = 0; t < TSTEPS; t++) {
        for (int cell = 0; cell < 2; cell++) {
            const int CC   = cell ? 128 : 96;
            const int hoff = cell ? HIDN : DIMX;
            const int Kt   = cell ? 640 : 480;
            const float* BG = cell ? bg1 : bg0;
            const float* BC = cell ? bc1 : bc0;
            float* H = cell ? sm.hB : sm.hA;
            const ushort* WGH = cell ? g_wg1h : g_wg0h;
            const ushort* WGL = cell ? g_wg1l : g_wg0l;
            const ushort* WCH = cell ? g_wc1h : g_wc0h;
            const ushort* WCL = cell ? g_wc1l : g_wc0l;

            // ===== gate Z build =====
            if (cell == 0) {
                for (int j = tid; j < RB * 24; j += THREADS) {
                    int r = j / 24, c = 4 * (j - 24 * r);
                    float4 v;
                    if (c < DIMX) {
                        int b = bbase + r / NNODE;
                        int n = r - NNODE * (r / NNODE);
                        v = *(const float4*)(x +
                            (((size_t)b * TSTEPS + t) * NNODE + n) * DIMX + c);
                    } else {
                        v = *(const float4*)(sm.hA + r * STH + (c - DIMX));
                    }
                    uint h0, l0, h1, l1;
                    split2(v.x, v.y, h0, l0);
                    split2(v.z, v.w, h1, l1);
                    int idx = r * STB + c;
                    *(uint2*)(sm.Zh + idx) = make_uint2(h0, h1);
                    *(uint2*)(sm.Zl + idx) = make_uint2(l0, l1);
                }
            } else {
                for (int j = tid; j < RB * 32; j += THREADS) {
                    int r = j >> 5, c = 4 * (j & 31);
                    float4 v = (c < HIDN)
                        ? *(const float4*)(sm.hA + r * STH + c)
                        : *(const float4*)(sm.hB + r * STH + (c - HIDN));
                    uint h0, l0, h1, l1;
                    split2(v.x, v.y, h0, l0);
                    split2(v.z, v.w, h1, l1);
                    int idx = r * STB + c;
                    *(uint2*)(sm.Zh + idx) = make_uint2(h0, h1);
                    *(uint2*)(sm.Zl + idx) = make_uint2(l0, l1);
                }
            }
            __syncthreads();

            // ===== GATE dconv (tensor) =====
            {
                float dg[40];
#pragma unroll
                for (int q = 0; q < 40; q++) dg[q] = 0.f;
#pragma unroll 1
                for (int m = 0; m < 5; m++) {
                    uint fhU, flU;
                    if (m == 0) { fhU = ZhU; flU = ZlU; }
                    else {
                        int s = (m - 1) >> 1;
                        int second = (m - 1) & 1;
                        const ushort* srch = second ? sm.Dah : sm.Zh;
                        const ushort* srcl = second ? sm.Dal : sm.Zl;
                        ushort* dsth = second ? sm.Dbh : sm.Dah;
                        ushort* dstl = second ? sm.Dbl : sm.Dal;
                        spmm4(sm.St2[s], srch, srcl, dsth, dstl,
                              second ? sm.Zh : (const ushort*)0,
                              second ? sm.Zl : (const ushort*)0,
                              CC, rbase_s, bloc_s, nlo_s, c0_s);
                        __syncthreads();
                        fhU = second ? DbhU : DahU;
                        flU = second ? DblU : DalU;
                    }
                    if (cell) gemm_gate_mma<128>(fhU, flU, WGH, WGL, Kt, m * 128,
                                                 16 * w, lr, lc, dg);
                    else      gemm_gate_mma<96> (fhU, flU, WGH, WGL, Kt, m * 96,
                                                 16 * w, lr, lc, dg);
                }
#pragma unroll
                for (int j = 0; j < 2; j++) {
                    int cb = 16 * w + 8 * j + 2 * lc;
                    float2 bv = *(const float2*)(BG + cb);
#pragma unroll
                    for (int mt = 0; mt < 5; mt++) {
                        float* d = dg + (j * 5 + mt) * 4;
                        int r0 = mt * 16 + lr, r1 = r0 + 8;
                        if (cb < HIDN) {
                            float2 h0 = *(const float2*)(H + r0 * STH + cb);
                            float v0 = sigm(d[0] + bv.x) * h0.x;
                            float v1 = sigm(d[1] + bv.y) * h0.y;
                            uint hh, ll;
                            split2(v0, v1, hh, ll);
                            *(uint*)(sm.Zh + r0 * STB + hoff + cb) = hh;
                            *(uint*)(sm.Zl + r0 * STB + hoff + cb) = ll;
                            if (mt < 4) {
                                float2 h1 = *(const float2*)(H + r1 * STH + cb);
                                float v2 = sigm(d[2] + bv.x) * h1.x;
                                float v3 = sigm(d[3] + bv.y) * h1.y;
                                split2(v2, v3, hh, ll);
                                *(uint*)(sm.Zh + r1 * STB + hoff + cb) = hh;
                                *(uint*)(sm.Zl + r1 * STB + hoff + cb) = ll;
                            }
                        } else {
                            int cu = cb - HIDN;
                            *(float2*)(sm.U + r0 * STH + cu) =
                                make_float2(sigm(d[0] + bv.x), sigm(d[1] + bv.y));
                            if (mt < 4)
                                *(float2*)(sm.U + r1 * STH + cu) =
                                    make_float2(sigm(d[2] + bv.x), sigm(d[3] + bv.y));
                        }
                    }
                }
            }
            __syncthreads();

            // ===== CANDIDATE dconv (tensor) + fused GRU update =====
            {
                float dc[20];
#pragma unroll
                for (int q = 0; q < 20; q++) dc[q] = 0.f;
#pragma unroll 1
                for (int m = 0; m < 5; m++) {
                    uint fhU, flU;
                    if (m == 0) { fhU = ZhU; flU = ZlU; }
                    else {
                        int s = (m - 1) >> 1;
                        int second = (m - 1) & 1;
                        const ushort* srch = second ? sm.Dah : sm.Zh;
                        const ushort* srcl = second ? sm.Dal : sm.Zl;
                        ushort* dsth = second ? sm.Dbh : sm.Dah;
                        ushort* dstl = second ? sm.Dbl : sm.Dal;
                        spmm4(sm.St2[s], srch, srcl, dsth, dstl,
                              second ? sm.Zh : (const ushort*)0,
                              second ? sm.Zl : (const ushort*)0,
                              CC, rbase_s, bloc_s, nlo_s, c0_s);
                        __syncthreads();
                        fhU = second ? DbhU : DahU;
                        flU = second ? DblU : DalU;
                    }
                    if (cell) gemm_cand_mma<128>(fhU, flU, WCH, WCL, Kt, m * 128,
                                                 8 * w, lr, lc, dc);
                    else      gemm_cand_mma<96> (fhU, flU, WCH, WCL, Kt, m * 96,
                                                 8 * w, lr, lc, dc);
                }
                {
                    int cb = 8 * w + 2 * lc;
                    float2 bv = *(const float2*)(BC + cb);
#pragma unroll
                    for (int mt = 0; mt < 5; mt++) {
                        float* d = dc + mt * 4;
                        int r0 = mt * 16 + lr, r1 = r0 + 8;
                        {
                            float c0v = tanh_(d[0] + bv.x), c1v = tanh_(d[1] + bv.y);
                            float2 u0 = *(const float2*)(sm.U + r0 * STH + cb);
                            float2 h0 = *(const float2*)(H + r0 * STH + cb);
                            *(float2*)(H + r0 * STH + cb) =
                                make_float2(c0v + u0.x * (h0.x - c0v),
                                            c1v + u0.y * (h0.y - c1v));
                        }
                        if (mt < 4) {
                            float c2v = tanh_(d[2] + bv.x), c3v = tanh_(d[3] + bv.y);
                            float2 u1 = *(const float2*)(sm.U + r1 * STH + cb);
                            float2 h1 = *(const float2*)(H + r1 * STH + cb);
                            *(float2*)(H + r1 * STH + cb) =
                                make_float2(c2v + u1.x * (h1.x - c2v),
                                            c3v + u1.y * (h1.y - c3v));
                        }
                    }
                }
            }
            __syncthreads();
        } // cell
    } // t

    // ---- epilogue ----
    if (tid < RB) {
        float acc = fcb[0];
#pragma unroll
        for (int c = 0; c < HIDN; c++)
            acc += fmaxf(sm.hB[tid * STH + c], 0.f) * fcw[c];
        sm.U[tid] = acc;
    }
    __syncthreads();
    if (tid < NB) {
        float mx = -3.4e38f;
#pragma unroll
        for (int n = 0; n < NNODE; n++)
            mx = fmaxf(mx, sm.U[tid * NNODE + n]);
        out[bbase + tid] = mx;
    }
}

extern "C" void kernel_launch(void* const* d_in, const int* in_sizes, int n_in,
                              void* d_out, int out_size)
{
    (void)in_sizes; (void)n_in; (void)out_size;
    const size_t shbytes = sizeof(Smem);
    cudaFuncSetAttribute(dcrnn_kernel,
                         cudaFuncAttributeMaxDynamicSharedMemorySize,
                         (int)shbytes);
    pack_kernel<<<(215040 + 255) / 256, 256>>>(
        (const float*)d_in[2], (const float*)d_in[4],
        (const float*)d_in[6], (const float*)d_in[8]);
    dcrnn_kernel<<<NBLK, THREADS, shbytes>>>(
        (const float*)d_in[0],  (const float*)d_in[1],
        (const float*)d_in[3],  (const float*)d_in[5],
        (const float*)d_in[7],  (const float*)d_in[9],
        (const float*)d_in[10], (const float*)d_in[11],
        (float*)d_out);
}